// round 4
// baseline (speedup 1.0000x reference)
#include <cuda_runtime.h>
#include <cuda_fp16.h>
#include <cstdint>

// Problem constants (fixed by the dataset)
#define NN 100000
#define EE 1600000
#define FF 128
#define GG 64
#define CC 3

#define SB 1024
#define NSB ((NN + SB - 1) / SB)   // 98

// Scratch: __device__ globals (no allocation allowed)
__device__ int    g_deg[NN];
__device__ float  g_dis[NN];
__device__ __half g_h1h[(size_t)NN * FF];  // GEMM output (fp16, gather-only consumer)
__device__ float  g_agg[(size_t)NN * FF];  // aggregation output (fp32)
__device__ float  g_sums[GG * FF];
__device__ float  g_cnt[GG];
__device__ int    g_rowoff[NN];
__device__ int    g_cursor[NN];
__device__ int    g_bsum[NSB];
__device__ int    g_csr_src[EE];
__device__ float  g_csr_coef[EE];

__device__ __forceinline__ void red_add_v4(float* addr, float x, float y, float z, float w) {
    asm volatile("red.global.add.v4.f32 [%0], {%1, %2, %3, %4};"
                 :: "l"(addr), "f"(x), "f"(y), "f"(z), "f"(w) : "memory");
}

// ---------------- init / degree / norm ----------------

__global__ void k_init() {
    int i = blockIdx.x * blockDim.x + threadIdx.x;
    if (i < NN) g_deg[i] = 1;             // self-loop
    if (i < GG * FF) g_sums[i] = 0.0f;
    if (i < GG) g_cnt[i] = 0.0f;
}

__global__ void k_count(const int* __restrict__ dst) {
    int e = blockIdx.x * blockDim.x + threadIdx.x;
    if (e < EE) atomicAdd(&g_deg[dst[e]], 1);
}

__global__ void k_dis(const int* __restrict__ batch) {
    int i = blockIdx.x * blockDim.x + threadIdx.x;
    if (i < NN) {
        g_dis[i] = rsqrtf((float)g_deg[i]);
        atomicAdd(&g_cnt[batch[i]], 1.0f);
    }
}

// ---------------- CSR build: 2-level exclusive scan + binning ----------------

__global__ __launch_bounds__(SB) void k_bsum() {
    __shared__ int sh[SB];
    int i = blockIdx.x * SB + threadIdx.x;
    sh[threadIdx.x] = (i < NN) ? (g_deg[i] - 1) : 0;
    __syncthreads();
    for (int s = SB / 2; s > 0; s >>= 1) {
        if (threadIdx.x < s) sh[threadIdx.x] += sh[threadIdx.x + s];
        __syncthreads();
    }
    if (threadIdx.x == 0) g_bsum[blockIdx.x] = sh[0];
}

__global__ void k_scan_bsum() {
    if (threadIdx.x == 0) {
        int acc = 0;
        for (int b = 0; b < NSB; b++) { int t = g_bsum[b]; g_bsum[b] = acc; acc += t; }
    }
}

__global__ __launch_bounds__(SB) void k_rowoff() {
    __shared__ int sh[SB];
    int i = blockIdx.x * SB + threadIdx.x;
    int v = (i < NN) ? (g_deg[i] - 1) : 0;
    sh[threadIdx.x] = v;
    __syncthreads();
    for (int off = 1; off < SB; off <<= 1) {
        int t = (threadIdx.x >= off) ? sh[threadIdx.x - off] : 0;
        __syncthreads();
        sh[threadIdx.x] += t;
        __syncthreads();
    }
    if (i < NN) {
        g_rowoff[i] = g_bsum[blockIdx.x] + sh[threadIdx.x] - v;  // exclusive
        g_cursor[i] = 0;
    }
}

__global__ void k_bin(const int* __restrict__ src, const int* __restrict__ dst) {
    int e = blockIdx.x * blockDim.x + threadIdx.x;
    if (e >= EE) return;
    int s = src[e], d = dst[e];
    int pos = atomicAdd(&g_cursor[d], 1);
    int idx = g_rowoff[d] + pos;
    g_csr_src[idx] = s;
    g_csr_coef[idx] = g_dis[s] * g_dis[d];
}

// ---------------- GEMM: h1h = fp16( act(A + bias) @ W ) ----------------
// BM=128, BN=128, BK=8, 256 threads, 8x8 thread tiles, double-buffered SMEM
// with register prefetch (one __syncthreads per K-iteration). act (bias+relu)
// fused on the A-load. Epilogue converts to fp16 (gather is the only consumer).

__global__ __launch_bounds__(256) void k_gemm(
    const float* __restrict__ Aext, int useAgg,
    const float* __restrict__ W,
    const float* __restrict__ bias, int act,
    int nrows)
{
    __shared__ float As[2][8][128];
    __shared__ float Bs[2][8][128];

    const float* A = useAgg ? g_agg : Aext;
    int block_row = blockIdx.x * 128;
    int tid = threadIdx.x;
    int tx = tid & 15;
    int ty = tid >> 4;

    int a_row  = tid >> 1;           // 0..127
    int a_col4 = (tid & 1) * 4;      // 0 or 4
    int b_row  = tid >> 5;           // 0..7
    int b_col  = (tid & 31) * 4;     // 0..124

    int a_grow = block_row + a_row;
    bool a_ok = a_grow < nrows;
    const float* aptr = A + (size_t)a_grow * FF + a_col4;

    float acc[8][8];
#pragma unroll
    for (int i = 0; i < 8; i++)
#pragma unroll
        for (int j = 0; j < 8; j++) acc[i][j] = 0.0f;

    // ---- load tile 0 ----
    float4 av = make_float4(0.f, 0.f, 0.f, 0.f);
    if (a_ok) av = *(const float4*)(aptr);
    if (act) {
        av.x = fmaxf(av.x + bias[a_col4 + 0], 0.0f);
        av.y = fmaxf(av.y + bias[a_col4 + 1], 0.0f);
        av.z = fmaxf(av.z + bias[a_col4 + 2], 0.0f);
        av.w = fmaxf(av.w + bias[a_col4 + 3], 0.0f);
    }
    float4 bv = *(const float4*)(W + (size_t)b_row * FF + b_col);
    As[0][a_col4 + 0][a_row] = av.x;
    As[0][a_col4 + 1][a_row] = av.y;
    As[0][a_col4 + 2][a_row] = av.z;
    As[0][a_col4 + 3][a_row] = av.w;
    *(float4*)&Bs[0][b_row][b_col] = bv;
    __syncthreads();

    int cur = 0;
    for (int k0 = 8; k0 < FF; k0 += 8) {
        // prefetch next tile into registers (LDG overlapped with compute below)
        float4 av2 = make_float4(0.f, 0.f, 0.f, 0.f);
        if (a_ok) av2 = *(const float4*)(aptr + k0);
        float4 bv2 = *(const float4*)(W + (size_t)(k0 + b_row) * FF + b_col);
        if (act) {
            av2.x = fmaxf(av2.x + bias[k0 + a_col4 + 0], 0.0f);
            av2.y = fmaxf(av2.y + bias[k0 + a_col4 + 1], 0.0f);
            av2.z = fmaxf(av2.z + bias[k0 + a_col4 + 2], 0.0f);
            av2.w = fmaxf(av2.w + bias[k0 + a_col4 + 3], 0.0f);
        }

        // compute on current buffer
#pragma unroll
        for (int k = 0; k < 8; k++) {
            float ar[8], br[8];
            *(float4*)&ar[0] = *(float4*)&As[cur][k][ty * 8];
            *(float4*)&ar[4] = *(float4*)&As[cur][k][ty * 8 + 4];
            *(float4*)&br[0] = *(float4*)&Bs[cur][k][tx * 8];
            *(float4*)&br[4] = *(float4*)&Bs[cur][k][tx * 8 + 4];
#pragma unroll
            for (int i = 0; i < 8; i++)
#pragma unroll
                for (int j = 0; j < 8; j++)
                    acc[i][j] = fmaf(ar[i], br[j], acc[i][j]);
        }

        // store prefetched tile into the other buffer (safe: last use of that
        // buffer completed before the previous __syncthreads)
        int nxt = cur ^ 1;
        As[nxt][a_col4 + 0][a_row] = av2.x;
        As[nxt][a_col4 + 1][a_row] = av2.y;
        As[nxt][a_col4 + 2][a_row] = av2.z;
        As[nxt][a_col4 + 3][a_row] = av2.w;
        *(float4*)&Bs[nxt][b_row][b_col] = bv2;
        __syncthreads();
        cur = nxt;
    }

    // last tile compute
#pragma unroll
    for (int k = 0; k < 8; k++) {
        float ar[8], br[8];
        *(float4*)&ar[0] = *(float4*)&As[cur][k][ty * 8];
        *(float4*)&ar[4] = *(float4*)&As[cur][k][ty * 8 + 4];
        *(float4*)&br[0] = *(float4*)&Bs[cur][k][tx * 8];
        *(float4*)&br[4] = *(float4*)&Bs[cur][k][tx * 8 + 4];
#pragma unroll
        for (int i = 0; i < 8; i++)
#pragma unroll
            for (int j = 0; j < 8; j++)
                acc[i][j] = fmaf(ar[i], br[j], acc[i][j]);
    }

    // fp16 epilogue
#pragma unroll
    for (int i = 0; i < 8; i++) {
        int grow = block_row + ty * 8 + i;
        if (grow < nrows) {
            __align__(16) __half2 hh[4];
            hh[0] = __floats2half2_rn(acc[i][0], acc[i][1]);
            hh[1] = __floats2half2_rn(acc[i][2], acc[i][3]);
            hh[2] = __floats2half2_rn(acc[i][4], acc[i][5]);
            hh[3] = __floats2half2_rn(acc[i][6], acc[i][7]);
            *(uint4*)(g_h1h + (size_t)grow * FF + tx * 8) = *(uint4*)hh;
        }
    }
}

// ---------------- CSR gather: agg[i] = dis[i]^2*h1[i] + sum_e coef_e * h1[src_e] ----
// One warp per node; lane owns features [lane*4, lane*4+4) as fp16 pairs
// (8-byte loads). 8-edge batched prefetch for deep MLP. do_pool fuses
// relu(.+b3) + mean-pool reduction for the last layer.

__device__ __forceinline__ void acc_half4(float4& acc, uint2 raw, float c) {
    float2 f0 = __half22float2(*(__half2*)&raw.x);
    float2 f1 = __half22float2(*(__half2*)&raw.y);
    acc.x = fmaf(c, f0.x, acc.x);
    acc.y = fmaf(c, f0.y, acc.y);
    acc.z = fmaf(c, f1.x, acc.z);
    acc.w = fmaf(c, f1.y, acc.w);
}

__global__ __launch_bounds__(256) void k_gather(
    const float* __restrict__ b3, const int* __restrict__ batch, int do_pool)
{
    int t = blockIdx.x * blockDim.x + threadIdx.x;
    int i = t >> 5, lane = t & 31;
    if (i >= NN) return;

    float di = g_dis[i];
    float c0 = di * di;
    float4 acc = make_float4(0.f, 0.f, 0.f, 0.f);
    {
        uint2 raw = *(const uint2*)(g_h1h + (size_t)i * FF + lane * 4);
        acc_half4(acc, raw, c0);
    }

    int start = g_rowoff[i];
    int cnt   = g_deg[i] - 1;

    for (int j0 = 0; j0 < cnt; j0 += 32) {
        int myj = j0 + lane;
        int   s = 0;
        float c = 0.0f;
        if (myj < cnt) {
            s = g_csr_src[start + myj];
            c = g_csr_coef[start + myj];
        }
        int m = min(32, cnt - j0);
        for (int u0 = 0; u0 < m; u0 += 8) {
            int mm = min(8, m - u0);
            uint2 v[8];
            float cf[8];
#pragma unroll
            for (int u = 0; u < 8; u++) {
                if (u < mm) {
                    int ss = __shfl_sync(0xffffffffu, s, u0 + u);
                    cf[u]  = __shfl_sync(0xffffffffu, c, u0 + u);
                    v[u] = *(const uint2*)(g_h1h + (size_t)ss * FF + lane * 4);
                }
            }
#pragma unroll
            for (int u = 0; u < 8; u++)
                if (u < mm) acc_half4(acc, v[u], cf[u]);
        }
    }

    if (do_pool) {
        const float4 b = *(const float4*)(b3 + lane * 4);
        float x = fmaxf(acc.x + b.x, 0.0f);
        float y = fmaxf(acc.y + b.y, 0.0f);
        float z = fmaxf(acc.z + b.z, 0.0f);
        float w = fmaxf(acc.w + b.w, 0.0f);
        int g = batch[i];
        red_add_v4(g_sums + (size_t)g * FF + lane * 4, x, y, z, w);
    } else {
        *(float4*)(g_agg + (size_t)i * FF + lane * 4) = acc;
    }
}

// ---------------- head: out[g] = (sums[g]/cnt[g]) @ Wc + bc ----------------

__global__ void k_final(const float* __restrict__ Wc, const float* __restrict__ bc,
                        float* __restrict__ out) {
    __shared__ float r[CC][FF];
    int g = blockIdx.x;
    int t = threadIdx.x;  // 128 threads
    float p = g_sums[g * FF + t] / fmaxf(g_cnt[g], 1.0f);
    r[0][t] = p * Wc[t * CC + 0];
    r[1][t] = p * Wc[t * CC + 1];
    r[2][t] = p * Wc[t * CC + 2];
    __syncthreads();
    for (int s = 64; s > 0; s >>= 1) {
        if (t < s) {
            r[0][t] += r[0][t + s];
            r[1][t] += r[1][t + s];
            r[2][t] += r[2][t + s];
        }
        __syncthreads();
    }
    if (t < CC) out[g * CC + t] = r[t][0] + bc[t];
}

// ---------------- launch ----------------

extern "C" void kernel_launch(void* const* d_in, const int* in_sizes, int n_in,
                              void* d_out, int out_size) {
    const float* x     = (const float*)d_in[0];
    const int*   ei    = (const int*)d_in[1];   // [2, E] int32
    const int*   batch = (const int*)d_in[2];
    const float* W1    = (const float*)d_in[3];
    const float* b1    = (const float*)d_in[4];
    const float* W2    = (const float*)d_in[5];
    const float* b2    = (const float*)d_in[6];
    const float* W3    = (const float*)d_in[7];
    const float* b3    = (const float*)d_in[8];
    const float* Wc    = (const float*)d_in[9];
    const float* bc    = (const float*)d_in[10];
    float* out = (float*)d_out;

    const int* src = ei;
    const int* dst = ei + EE;

    const int T = 256;
    int nb_n  = (NN + T - 1) / T;
    int nb_e  = (EE + T - 1) / T;
    int nb_nw = ((size_t)NN * 32 + T - 1) / T;       // warp-per-node kernels
    int nb_g  = (NN + 127) / 128;                    // GEMM row blocks

    // Graph preprocessing (once per launch)
    k_init<<<nb_n, T>>>();
    k_count<<<nb_e, T>>>(dst);
    k_dis<<<nb_n, T>>>(batch);
    k_bsum<<<NSB, SB>>>();
    k_scan_bsum<<<1, 32>>>();
    k_rowoff<<<NSB, SB>>>();
    k_bin<<<nb_e, T>>>(src, dst);

    // Layer 1: h1 = x @ W1 ; aggregate (b1+relu deferred into next GEMM load)
    k_gemm<<<nb_g, T>>>(x, 0, W1, nullptr, 0, NN);
    k_gather<<<nb_nw, T>>>(nullptr, nullptr, 0);

    // Layer 2
    k_gemm<<<nb_g, T>>>(nullptr, 1, W2, b1, 1, NN);
    k_gather<<<nb_nw, T>>>(nullptr, nullptr, 0);

    // Layer 3 (gather fused with relu(.+b3) + mean-pool reduction)
    k_gemm<<<nb_g, T>>>(nullptr, 1, W3, b2, 1, NN);
    k_gather<<<nb_nw, T>>>(b3, batch, 1);

    // Classify
    k_final<<<GG, FF>>>(Wc, bc, out);
}